// round 14
// baseline (speedup 1.0000x reference)
#include <cuda_runtime.h>
#include <cuda_bf16.h>
#include <math.h>
#include <stdint.h>

// ---------------------------------------------------------------------------
// GGNN forward. GEMMs on tensor cores via portable mma.sync (bf16, fp32 acc)
// with bf16x3 split emulation: C = Ah*Bh + Al*Bh + Ah*Bl  (residual ~2^-18).
// R13 changes:
//   * activations stored as bf16 hi/lo PLANES in global, split once at the
//     producer epilogue; GEMM A path is pure ldmatrix (no cvt in hot loop)
//   * gather/GRU/seg_sum read (hi+lo), write planes
//   * CSR build merged 13 -> 6 launches
// ---------------------------------------------------------------------------

#define HD 150          // feature dim
#define LD 160          // gate buffer leading dim (fp32)
#define PS 168          // activation plane leading dim (bf16), 336B rows
#define NMAX 100000
#define EMAX 500000
#define GMAX 16
#define NMATS 10        // W1_0,W2_0,W1_1,W2_1, Wih x3, Whh x3

#define BM 64           // rows per m-tile
#define KTI 10          // k chunks of 16 (K=160, pads are zero)

// smem layout (bytes). Rows padded to 336B -> conflict-free ldmatrix.
#define WSTRIDE 336
#define O_WHI 0
#define O_WLO 53760                    // 160*336
#define O_A0  107520                   // A buf0: hi(21504) + lo(21504)
#define O_A1  150528
#define A_PL  21504                    // one A plane (64*336)
#define O_BIAS 193536
#define SMEM_TOTAL 194176

static constexpr size_t GS = (size_t)NMAX * LD;   // gate buffer stride

// ---- scratch (device globals, zero-initialized at module load) ----
__device__ float g_gate[6 * (size_t)NMAX * LD];   // ir,iz,in,hr,hz,hn (fp32)
__device__ float g_graph[GMAX * HD];
__device__ __align__(16) __nv_bfloat16 g_h_hi [NMAX * PS];
__device__ __align__(16) __nv_bfloat16 g_h_lo [NMAX * PS];
__device__ __align__(16) __nv_bfloat16 g_t0_hi[NMAX * PS];
__device__ __align__(16) __nv_bfloat16 g_t0_lo[NMAX * PS];
__device__ __align__(16) __nv_bfloat16 g_t1_hi[NMAX * PS];
__device__ __align__(16) __nv_bfloat16 g_t1_lo[NMAX * PS];
__device__ __align__(16) __nv_bfloat16 g_z0_hi[NMAX * PS];
__device__ __align__(16) __nv_bfloat16 g_z0_lo[NMAX * PS];
__device__ __align__(16) __nv_bfloat16 g_z1_hi[NMAX * PS];
__device__ __align__(16) __nv_bfloat16 g_z1_lo[NMAX * PS];
__device__ __align__(16) __nv_bfloat16 g_in_hi[NMAX * PS];
__device__ __align__(16) __nv_bfloat16 g_in_lo[NMAX * PS];
__device__ __align__(16) __nv_bfloat16 g_Whi[NMATS * LD * LD];  // [mat][n][k]
__device__ __align__(16) __nv_bfloat16 g_Wlo[NMATS * LD * LD];

// CSR (rebuilt every launch; edges are static inputs)
__device__ int g_cnt [2][NMAX];
__device__ int g_off [2][NMAX + 1];
__device__ int g_cur [2][NMAX];
__device__ int g_srcs[2][EMAX];
__device__ int g_bsum[2][128];

// ---------------------------------------------------------------------------
// helpers
// ---------------------------------------------------------------------------
__device__ __forceinline__ uint32_t smem_u32(const void* p) {
    uint32_t a;
    asm("{ .reg .u64 t; cvta.to.shared.u64 t, %1; cvt.u32.u64 %0, t; }"
        : "=r"(a) : "l"(p));
    return a;
}
__device__ __forceinline__ void cp16(uint32_t dst, const void* src) {
    asm volatile("cp.async.cg.shared.global [%0], [%1], 16;"
                 :: "r"(dst), "l"(src));
}
#define CP_COMMIT() asm volatile("cp.async.commit_group;" ::: "memory")
#define CP_WAIT(n)  asm volatile("cp.async.wait_group %0;" :: "n"(n) : "memory")

__device__ __forceinline__ void ldmx4(uint32_t* r, uint32_t addr) {
    asm volatile("ldmatrix.sync.aligned.m8n8.x4.shared.b16 {%0,%1,%2,%3}, [%4];"
                 : "=r"(r[0]), "=r"(r[1]), "=r"(r[2]), "=r"(r[3]) : "r"(addr));
}
__device__ __forceinline__ void mma16816(float* c, const uint32_t* a,
                                         const uint32_t* b) {
    asm volatile("mma.sync.aligned.m16n8k16.row.col.f32.bf16.bf16.f32 "
                 "{%0,%1,%2,%3}, {%4,%5,%6,%7}, {%8,%9}, {%0,%1,%2,%3};"
                 : "+f"(c[0]), "+f"(c[1]), "+f"(c[2]), "+f"(c[3])
                 : "r"(a[0]), "r"(a[1]), "r"(a[2]), "r"(a[3]),
                   "r"(b[0]), "r"(b[1]));
}
__device__ __forceinline__ uint32_t f2bf2(float a, float b) {
    __nv_bfloat162 h = __floats2bfloat162_rn(a, b);
    return *reinterpret_cast<uint32_t*>(&h);
}
__device__ __forceinline__ uint32_t lo2(float2 v, uint32_t hi) {
    const float hx = __uint_as_float(hi << 16);
    const float hy = __uint_as_float(hi & 0xffff0000u);
    return f2bf2(v.x - hx, v.y - hy);
}
__device__ __forceinline__ float bflo(uint32_t u) { return __uint_as_float(u << 16); }
__device__ __forceinline__ float bfhi(uint32_t u) { return __uint_as_float(u & 0xffff0000u); }

// ---------------------------------------------------------------------------
// Weight pre-split: 10 matrices -> [LD x LD] bf16 hi/lo in global.
// ---------------------------------------------------------------------------
__global__ void make_wsplit(const float* __restrict__ W1_0, const float* __restrict__ W2_0,
                            const float* __restrict__ W1_1, const float* __restrict__ W2_1,
                            const float* __restrict__ Wih,  const float* __restrict__ Whh)
{
    const int total = NMATS * LD * LD;
    for (int idx = blockIdx.x * blockDim.x + threadIdx.x; idx < total;
         idx += gridDim.x * blockDim.x) {
        const int mat = idx / (LD * LD);
        const int rem = idx - mat * (LD * LD);
        const int r = rem / LD;
        const int k = rem - r * LD;
        float v = 0.f;
        if (r < HD && k < HD) {
            if      (mat == 0) v = W1_0[r * HD + k];
            else if (mat == 1) v = W2_0[r * HD + k];
            else if (mat == 2) v = W1_1[r * HD + k];
            else if (mat == 3) v = W2_1[r * HD + k];
            else if (mat <= 6) v = Wih[((mat - 4) * HD + r) * HD + k];
            else               v = Whh[((mat - 7) * HD + r) * HD + k];
        }
        __nv_bfloat16 hi = __float2bfloat16_rn(v);
        __nv_bfloat16 lo = __float2bfloat16_rn(v - __bfloat162float(hi));
        g_Whi[idx] = hi;
        g_Wlo[idx] = lo;
    }
}

// ---------------------------------------------------------------------------
// Multi-matrix persistent tensor-core GEMM; A from bf16 hi/lo planes.
// Output: bf16 hi/lo planes (fpout=0) or fp32 gate buffer (fpout=1).
// ---------------------------------------------------------------------------
struct Jobs {
    const __nv_bfloat16* Ahi[6];
    const __nv_bfloat16* Alo[6];
    __nv_bfloat16*       Chi[6];
    __nv_bfloat16*       Clo[6];
    float*               Cf[6];
    const float*         bias[6];
    int                  mat[6];
    int                  fpout[6];
    int                  nmats;
    int                  act;
};

__device__ __forceinline__ void load_a_tile(uint32_t dstBase,
                                            const __nv_bfloat16* Ahi,
                                            const __nv_bfloat16* Alo,
                                            int t, int M, int tid)
{
    for (int jj = tid; jj < 2 * 64 * 21; jj += 256) {
        const int plane = jj >= 64 * 21;
        const int j2 = plane ? jj - 64 * 21 : jj;
        const int r = j2 / 21, u = j2 - r * 21;
        const int grow = min(t * BM + r, M - 1);
        cp16(dstBase + (plane ? A_PL : 0) + r * WSTRIDE + u * 16,
             (plane ? Alo : Ahi) + (size_t)grow * PS + u * 8);
    }
}

__global__ __launch_bounds__(256, 1)
void gemm_multi(Jobs j, int tiles, int M)
{
    extern __shared__ char smem[];
    const uint32_t sb = smem_u32(smem);
    const int tid  = threadIdx.x;
    const int wid  = tid >> 5;
    const int lane = tid & 31;
    const int warpM = wid & 3;          // m16 slice within BM=64
    const int warpN = wid >> 2;         // n80 half

    const int units = j.nmats * tiles;
    const int u0 = (int)(((long long)units * blockIdx.x) / gridDim.x);
    const int u1 = (int)(((long long)units * (blockIdx.x + 1)) / gridDim.x);
    if (u0 >= u1) return;

    // per-lane ldmatrix B addresses (5 ntile-pairs), kt advances by 32B
    const int gB = lane >> 3;
    const int rB = (lane & 7) + ((gB >> 1) << 3);
    const int kB = (gB & 1) << 3;
    uint32_t bAddr[5];
    #pragma unroll
    for (int p = 0; p < 5; p++)
        bAddr[p] = sb + O_WHI + (warpN * 80 + p * 16 + rB) * WSTRIDE + kB * 2;

    // per-lane ldmatrix A offset within a plane (m16 rows x k16):
    // lanes 0-7: rows 0-7 k0 | 8-15: rows 8-15 k0 | 16-23: rows 0-7 k8 | 24-31: rows 8-15 k8
    const int rowL = warpM * 16 + (lane & 7) + (((lane >> 3) & 1) << 3);
    const uint32_t aOff = (uint32_t)(rowL * WSTRIDE + ((lane >> 4) << 4));

    // ---- prologue: A(u0) into buf0 ----
    {
        const int m0 = u0 / tiles, t0 = u0 - m0 * tiles;
        load_a_tile(sb + O_A0, j.Ahi[m0], j.Alo[m0], t0, M, tid);
        CP_COMMIT();
    }

    int curMat = -1;
    int i = 0;
    for (int u = u0; u < u1; u++, i++) {
        const int m = u / tiles;
        const int t = u - m * tiles;
        const int cur = i & 1;

        if (m != curMat) {                 // (re)load W + bias for this job
            curMat = m;
            const int mat = j.mat[m];
            const __nv_bfloat16* Wh = g_Whi + (size_t)mat * LD * LD;
            const __nv_bfloat16* Wl = g_Wlo + (size_t)mat * LD * LD;
            for (int jj = tid; jj < 2 * LD * 20; jj += 256) {
                const int s  = (jj >= LD * 20);
                const int j2 = s ? (jj - LD * 20) : jj;
                const int r  = j2 / 20;
                const int uu = j2 - r * 20;
                cp16(sb + (s ? O_WLO : O_WHI) + r * WSTRIDE + uu * 16,
                     (s ? Wl : Wh) + (size_t)r * LD + uu * 8);
            }
            CP_COMMIT();
            const float* bp = j.bias[m];
            for (int c = tid; c < LD; c += 256)
                *reinterpret_cast<float*>(smem + O_BIAS + c * 4) =
                    (c < HD) ? bp[c] : 0.f;
        }

        // ---- prefetch A(u+1) into the other buffer ----
        if (u + 1 < u1) {
            const int mn = (u + 1) / tiles;
            const int tn = (u + 1) - mn * tiles;
            load_a_tile(sb + (cur ? O_A0 : O_A1), j.Ahi[mn], j.Alo[mn], tn, M, tid);
            CP_COMMIT();
            CP_WAIT(1);    // A(u) + W done; A(u+1) may stay in flight
        } else {
            CP_WAIT(0);
        }
        __syncthreads();

        const uint32_t sA = sb + (cur ? O_A1 : O_A0);

        float acc[10][4];
        #pragma unroll
        for (int n = 0; n < 10; n++)
            #pragma unroll
            for (int q = 0; q < 4; q++) acc[n][q] = 0.f;

        #pragma unroll
        for (int kt = 0; kt < KTI; kt++) {
            uint32_t ah[4], al[4];
            ldmx4(ah, sA + aOff + kt * 32);
            ldmx4(al, sA + A_PL + aOff + kt * 32);

            // product-major order: 10 independent MMAs between acc reuses
            uint32_t bfr[5][4];
            #pragma unroll
            for (int p = 0; p < 5; p++) ldmx4(bfr[p], bAddr[p] + kt * 32);
            #pragma unroll
            for (int p = 0; p < 5; p++) {
                mma16816(acc[2 * p],     ah, bfr[p]);
                mma16816(acc[2 * p + 1], ah, bfr[p] + 2);
            }
            #pragma unroll
            for (int p = 0; p < 5; p++) {
                mma16816(acc[2 * p],     al, bfr[p]);
                mma16816(acc[2 * p + 1], al, bfr[p] + 2);
            }
            #pragma unroll
            for (int p = 0; p < 5; p++)
                ldmx4(bfr[p], bAddr[p] + kt * 32 + (O_WLO - O_WHI));
            #pragma unroll
            for (int p = 0; p < 5; p++) {
                mma16816(acc[2 * p],     ah, bfr[p]);
                mma16816(acc[2 * p + 1], ah, bfr[p] + 2);
            }
        }

        // ---- epilogue: bias + act; write bf16 planes or fp32 gates ----
        {
            const int r0 = t * BM + warpM * 16 + (lane >> 2);
            const int fp = j.fpout[m];
            float* Cf = j.Cf[m];
            __nv_bfloat16* Chi = j.Chi[m];
            __nv_bfloat16* Clo = j.Clo[m];
            #pragma unroll
            for (int n = 0; n < 10; n++) {
                const int c0 = warpN * 80 + n * 8 + (lane & 3) * 2;
                const float b0 = *reinterpret_cast<float*>(smem + O_BIAS + c0 * 4);
                const float b1 = *reinterpret_cast<float*>(smem + O_BIAS + (c0 + 1) * 4);
                float x0 = acc[n][0] + b0, x1 = acc[n][1] + b1;
                float x2 = acc[n][2] + b0, x3 = acc[n][3] + b1;
                if (j.act) {
                    x0 = x0 > 0.f ? x0 : 0.01f * x0;
                    x1 = x1 > 0.f ? x1 : 0.01f * x1;
                    x2 = x2 > 0.f ? x2 : 0.01f * x2;
                    x3 = x3 > 0.f ? x3 : 0.01f * x3;
                }
                if (fp) {
                    if (r0 < M)
                        *reinterpret_cast<float2*>(Cf + (size_t)r0 * LD + c0) =
                            make_float2(x0, x1);
                    if (r0 + 8 < M)
                        *reinterpret_cast<float2*>(Cf + (size_t)(r0 + 8) * LD + c0) =
                            make_float2(x2, x3);
                } else {
                    if (r0 < M) {
                        const uint32_t hp = f2bf2(x0, x1);
                        *reinterpret_cast<uint32_t*>(Chi + (size_t)r0 * PS + c0) = hp;
                        *reinterpret_cast<uint32_t*>(Clo + (size_t)r0 * PS + c0) =
                            lo2(make_float2(x0, x1), hp);
                    }
                    if (r0 + 8 < M) {
                        const uint32_t hp = f2bf2(x2, x3);
                        *reinterpret_cast<uint32_t*>(Chi + (size_t)(r0 + 8) * PS + c0) = hp;
                        *reinterpret_cast<uint32_t*>(Clo + (size_t)(r0 + 8) * PS + c0) =
                            lo2(make_float2(x2, x3), hp);
                    }
                }
            }
        }
        __syncthreads();   // protect A/W/bias buffers before next iteration
    }
}

// ---------------------------------------------------------------------------
// CSR build (merged, 6 launches). counts -> offsets -> cursors -> fill.
// ---------------------------------------------------------------------------
#define SCAN_BLK 1024
#define SCAN_NB  ((NMAX + SCAN_BLK - 1) / SCAN_BLK)   // 98

__global__ void csr_zero()
{
    int* c = &g_cnt[0][0];
    for (int i = blockIdx.x * blockDim.x + threadIdx.x; i < 2 * NMAX;
         i += gridDim.x * blockDim.x) c[i] = 0;
}
__global__ void csr_hist2(const int* __restrict__ e0, int E0,
                          const int* __restrict__ e1, int E1)
{
    const int total = E0 + E1;
    for (int i = blockIdx.x * blockDim.x + threadIdx.x; i < total;
         i += gridDim.x * blockDim.x) {
        if (i < E0) atomicAdd(&g_cnt[0][e0[2 * i]], 1);
        else        atomicAdd(&g_cnt[1][e1[2 * (i - E0)]], 1);
    }
}
__global__ void csr_scan1()
{
    const int s = blockIdx.y;
    __shared__ int sh[SCAN_BLK];
    const int t = threadIdx.x;
    const int idx = blockIdx.x * SCAN_BLK + t;
    int v = (idx < NMAX) ? g_cnt[s][idx] : 0;
    sh[t] = v; __syncthreads();
    #pragma unroll
    for (int d = 1; d < SCAN_BLK; d <<= 1) {
        int x = (t >= d) ? sh[t - d] : 0;
        __syncthreads();
        sh[t] += x;
        __syncthreads();
    }
    if (idx < NMAX) g_off[s][idx + 1] = sh[t];
    if (t == SCAN_BLK - 1) g_bsum[s][blockIdx.x] = sh[t];
    if (idx == 0) g_off[s][0] = 0;
}
__global__ void csr_scan2both()
{
    if (threadIdx.x == 0) {
        for (int s = 0; s < 2; s++) {
            int acc = 0;
            for (int b = 0; b < SCAN_NB; b++) {
                int t = g_bsum[s][b];
                g_bsum[s][b] = acc;
                acc += t;
            }
        }
    }
}
__global__ void csr_scan3c()   // finalize offsets + write cursors
{
    const int s = blockIdx.y;
    for (int idx = blockIdx.x * blockDim.x + threadIdx.x; idx < NMAX;
         idx += gridDim.x * blockDim.x) {
        const int v = g_off[s][idx + 1] + g_bsum[s][idx >> 10];
        g_off[s][idx + 1] = v;
        if (idx + 1 < NMAX) g_cur[s][idx + 1] = v;
        if (idx == 0) g_cur[s][0] = 0;
    }
}
__global__ void csr_fill2(const int* __restrict__ e0, int E0,
                          const int* __restrict__ e1, int E1)
{
    const int total = E0 + E1;
    for (int i = blockIdx.x * blockDim.x + threadIdx.x; i < total;
         i += gridDim.x * blockDim.x) {
        const int s = (i < E0) ? 0 : 1;
        const int* e = (s == 0) ? e0 : e1;
        const int k = (s == 0) ? i : i - E0;
        const int dst = e[2 * k];
        const int src = e[2 * k + 1];
        const int slot = atomicAdd(&g_cur[s][dst], 1);
        g_srcs[s][slot] = src;
    }
}

// ---------------------------------------------------------------------------
// Fused gather over BOTH edge sets, bf16 planes in/out:
//   inc[v] = sum z0[src] + sum z1[src]   (accumulate hi+lo in fp32)
// One warp per node; lanes 0-18 each own 8 cols (152 cols, pads zero).
// ---------------------------------------------------------------------------
__global__ void gather_both(int N)
{
    const int v = (int)((blockIdx.x * blockDim.x + threadIdx.x) >> 5);
    const int lane = threadIdx.x & 31;
    if (v >= N) return;
    const bool act = lane < 19;
    const int col = lane * 8;
    float a[8];
    #pragma unroll
    for (int q = 0; q < 8; q++) a[q] = 0.f;

    #pragma unroll
    for (int s = 0; s < 2; s++) {
        const __nv_bfloat16* zh = s ? g_z1_hi : g_z0_hi;
        const __nv_bfloat16* zl = s ? g_z1_lo : g_z0_lo;
        const int st = g_off[s][v];
        const int en = g_off[s][v + 1];
        for (int i = st; i < en; i++) {
            const int src = g_srcs[s][i];
            if (act) {
                const uint4 hv = *reinterpret_cast<const uint4*>(
                    zh + (size_t)src * PS + col);
                const uint4 lv = *reinterpret_cast<const uint4*>(
                    zl + (size_t)src * PS + col);
                a[0] += bflo(hv.x) + bflo(lv.x);  a[1] += bfhi(hv.x) + bfhi(lv.x);
                a[2] += bflo(hv.y) + bflo(lv.y);  a[3] += bfhi(hv.y) + bfhi(lv.y);
                a[4] += bflo(hv.z) + bflo(lv.z);  a[5] += bfhi(hv.z) + bfhi(lv.z);
                a[6] += bflo(hv.w) + bflo(lv.w);  a[7] += bfhi(hv.w) + bfhi(lv.w);
            }
        }
    }
    if (act) {
        uint4 oh, ol;
        oh.x = f2bf2(a[0], a[1]); ol.x = lo2(make_float2(a[0], a[1]), oh.x);
        oh.y = f2bf2(a[2], a[3]); ol.y = lo2(make_float2(a[2], a[3]), oh.y);
        oh.z = f2bf2(a[4], a[5]); ol.z = lo2(make_float2(a[4], a[5]), oh.z);
        oh.w = f2bf2(a[6], a[7]); ol.w = lo2(make_float2(a[6], a[7]), oh.w);
        *reinterpret_cast<uint4*>(g_in_hi + (size_t)v * PS + col) = oh;
        *reinterpret_cast<uint4*>(g_in_lo + (size_t)v * PS + col) = ol;
    }
}

__global__ void zero_f4(float4* __restrict__ p, int n4)
{
    int i = blockIdx.x * blockDim.x + threadIdx.x;
    const int stride = gridDim.x * blockDim.x;
    for (; i < n4; i += stride) p[i] = make_float4(0.f, 0.f, 0.f, 0.f);
}

__global__ void init_h(const float* __restrict__ nodes, int N)
{
    int idx = blockIdx.x * blockDim.x + threadIdx.x;
    const int total = N * PS;
    const int stride = gridDim.x * blockDim.x;
    for (; idx < total; idx += stride) {
        const int r = idx / PS, c = idx - r * PS;
        const float v = (c < HD) ? nodes[r * HD + c] : 0.f;
        const __nv_bfloat16 hi = __float2bfloat16_rn(v);
        g_h_hi[idx] = hi;
        g_h_lo[idx] = __float2bfloat16_rn(v - __bfloat162float(hi));
    }
}

// GRU combine: h = (1-z)*tanh(in + r*hn) + z*h. Gates fp32, h bf16 planes.
// Unit = (row, 4 cols). Pad cols 150-159: gates 0 -> h' = 0.5*h = 0 (h pad 0).
__global__ void gru_gate4(const float* __restrict__ gates, int N)
{
    const int units = N * 40;
    int idx = blockIdx.x * blockDim.x + threadIdx.x;
    const int stride = gridDim.x * blockDim.x;
    for (; idx < units; idx += stride) {
        const int r = idx / 40;
        const int c = (idx - r * 40) * 4;
        const size_t gb = (size_t)r * LD + c;
        const float4 ir = *reinterpret_cast<const float4*>(gates + 0 * GS + gb);
        const float4 iz = *reinterpret_cast<const float4*>(gates + 1 * GS + gb);
        const float4 in_ = *reinterpret_cast<const float4*>(gates + 2 * GS + gb);
        const float4 hr = *reinterpret_cast<const float4*>(gates + 3 * GS + gb);
        const float4 hz = *reinterpret_cast<const float4*>(gates + 4 * GS + gb);
        const float4 hn = *reinterpret_cast<const float4*>(gates + 5 * GS + gb);
        const size_t hb = (size_t)r * PS + c;
        const uint2 hv = *reinterpret_cast<const uint2*>(g_h_hi + hb);
        const uint2 lv = *reinterpret_cast<const uint2*>(g_h_lo + hb);
        float h[4];
        h[0] = bflo(hv.x) + bflo(lv.x);  h[1] = bfhi(hv.x) + bfhi(lv.x);
        h[2] = bflo(hv.y) + bflo(lv.y);  h[3] = bfhi(hv.y) + bfhi(lv.y);
        float o[4];
        #pragma unroll
        for (int q = 0; q < 4; q++) {
            const float irv = (&ir.x)[q], izv = (&iz.x)[q], inv = (&in_.x)[q];
            const float hrv = (&hr.x)[q], hzv = (&hz.x)[q], hnv = (&hn.x)[q];
            const float rr = 1.f / (1.f + expf(-(irv + hrv)));
            const float zz = 1.f / (1.f + expf(-(izv + hzv)));
            const float nn = tanhf(inv + rr * hnv);
            o[q] = (1.f - zz) * nn + zz * h[q];
        }
        uint2 oh, ol;
        oh.x = f2bf2(o[0], o[1]); ol.x = lo2(make_float2(o[0], o[1]), oh.x);
        oh.y = f2bf2(o[2], o[3]); ol.y = lo2(make_float2(o[2], o[3]), oh.y);
        *reinterpret_cast<uint2*>(g_h_hi + hb) = oh;
        *reinterpret_cast<uint2*>(g_h_lo + hb) = ol;
    }
}

// Segment sum over sorted graph_ids (h = hi + lo planes).
__global__ void seg_sum(const int* __restrict__ gid,
                        float* __restrict__ gout, int N)
{
    const int f = threadIdx.x;
    const int r0 = blockIdx.x * 256;
    const int r1 = min(r0 + 256, N);
    float acc = 0.f;
    int cur = -1;
    for (int r = r0; r < r1; r++) {
        const int id = gid[r];
        if (id != cur) {
            if (cur >= 0 && f < HD) atomicAdd(&gout[cur * HD + f], acc);
            acc = 0.f; cur = id;
        }
        if (f < HD) {
            const size_t p = (size_t)r * PS + f;
            acc += __bfloat162float(g_h_hi[p]) + __bfloat162float(g_h_lo[p]);
        }
    }
    if (cur >= 0 && f < HD) atomicAdd(&gout[cur * HD + f], acc);
}

// Head MLP (16 rows): one block.
__global__ void mlp_head(const float* __restrict__ gg,
                         const float* __restrict__ ptype,
                         const float* __restrict__ fc1W, const float* __restrict__ fc1b,
                         const float* __restrict__ fc2W, const float* __restrict__ fc2b,
                         const float* __restrict__ fcLW, const float* __restrict__ fcLb,
                         float* __restrict__ out)
{
    __shared__ float sx [GMAX * 151];
    __shared__ float sy1[GMAX * 80];
    __shared__ float sy2[GMAX * 80];
    const int tid = threadIdx.x;

    for (int p = tid; p < GMAX * HD; p += blockDim.x) {
        const int g = p / HD, k = p - g * HD;
        float lg = logf(gg[p]);
        if (isnan(lg)) lg = 0.f;
        sx[g * 151 + k] = fmaxf(lg, 0.f);
    }
    for (int p = tid; p < GMAX; p += blockDim.x) sx[p * 151 + 150] = ptype[p];
    __syncthreads();

    for (int p = tid; p < GMAX * 80; p += blockDim.x) {
        const int g = p / 80, o = p - g * 80;
        float s = fc1b[o];
        for (int k = 0; k < 151; k++) s += fc1W[o * 151 + k] * sx[g * 151 + k];
        sy1[g * 80 + o] = s > 0.f ? s : 0.01f * s;
    }
    __syncthreads();

    for (int p = tid; p < GMAX * 80; p += blockDim.x) {
        const int g = p / 80, o = p - g * 80;
        float s = fc2b[o];
        for (int k = 0; k < 80; k++) s += fc2W[o * 80 + k] * sy1[g * 80 + k];
        sy2[g * 80 + o] = s > 0.f ? s : 0.01f * s;
    }
    __syncthreads();

    for (int p = tid; p < GMAX * 10; p += blockDim.x) {
        const int g = p / 10, o = p - g * 10;
        float s = fcLb[o];
        for (int k = 0; k < 80; k++) s += fcLW[o * 80 + k] * sy2[g * 80 + k];
        out[g * 10 + o] = s;
    }
}

// ---------------------------------------------------------------------------
extern "C" void kernel_launch(void* const* d_in, const int* in_sizes, int n_in,
                              void* d_out, int out_size)
{
    const float* nodes = (const float*)d_in[0];
    const float* ptype = (const float*)d_in[1];
    const float* W1_0  = (const float*)d_in[2];  const float* b1_0 = (const float*)d_in[3];
    const float* W2_0  = (const float*)d_in[4];  const float* b2_0 = (const float*)d_in[5];
    const float* W1_1  = (const float*)d_in[6];  const float* b1_1 = (const float*)d_in[7];
    const float* W2_1  = (const float*)d_in[8];  const float* b2_1 = (const float*)d_in[9];
    const float* Wih   = (const float*)d_in[10]; const float* bih  = (const float*)d_in[11];
    const float* Whh   = (const float*)d_in[12]; const float* bhh  = (const float*)d_in[13];
    const float* fc1W  = (const float*)d_in[14]; const float* fc1b = (const float*)d_in[15];
    const float* fc2W  = (const float*)d_in[16]; const float* fc2b = (const float*)d_in[17];
    const float* fcLW  = (const float*)d_in[18]; const float* fcLb = (const float*)d_in[19];
    const int* edges0  = (const int*)d_in[20];
    const int* edges1  = (const int*)d_in[21];
    const int* gids    = (const int*)d_in[22];

    const int N  = in_sizes[0] / HD;
    const int E0 = in_sizes[20] / 2;
    const int E1 = in_sizes[21] / 2;
    const int PASSES = 4;

    __nv_bfloat16 *phh, *phl, *pt0h, *pt0l, *pt1h, *pt1l;
    __nv_bfloat16 *pz0h, *pz0l, *pz1h, *pz1l, *pih, *pil;
    float *pg, *pgraph;
    cudaGetSymbolAddress((void**)&phh,  g_h_hi);  cudaGetSymbolAddress((void**)&phl,  g_h_lo);
    cudaGetSymbolAddress((void**)&pt0h, g_t0_hi); cudaGetSymbolAddress((void**)&pt0l, g_t0_lo);
    cudaGetSymbolAddress((void**)&pt1h, g_t1_hi); cudaGetSymbolAddress((void**)&pt1l, g_t1_lo);
    cudaGetSymbolAddress((void**)&pz0h, g_z0_hi); cudaGetSymbolAddress((void**)&pz0l, g_z0_lo);
    cudaGetSymbolAddress((void**)&pz1h, g_z1_hi); cudaGetSymbolAddress((void**)&pz1l, g_z1_lo);
    cudaGetSymbolAddress((void**)&pih,  g_in_hi); cudaGetSymbolAddress((void**)&pil,  g_in_lo);
    cudaGetSymbolAddress((void**)&pg,     g_gate);
    cudaGetSymbolAddress((void**)&pgraph, g_graph);

    cudaFuncSetAttribute(gemm_multi, cudaFuncAttributeMaxDynamicSharedMemorySize,
                         SMEM_TOTAL);

    const int tiles = (N + BM - 1) / BM;
    const int gatherBlocks = (N * 32 + 255) / 256;

    make_wsplit<<<256, 256>>>(W1_0, W2_0, W1_1, W2_1, Wih, Whh);
    init_h<<<2048, 256>>>(nodes, N);

    // ---- CSR build (both edge sets, merged launches) ----
    csr_zero<<<256, 256>>>();
    csr_hist2<<<512, 256>>>(edges0, E0, edges1, E1);
    csr_scan1<<<dim3(SCAN_NB, 2), SCAN_BLK>>>();
    csr_scan2both<<<1, 32>>>();
    csr_scan3c<<<dim3(128, 2), 256>>>();
    csr_fill2<<<512, 256>>>(edges0, E0, edges1, E1);

    // ---- job tables ----
    Jobs L1 = {};      // t0 = lrelu(h W1_0^T + b1_0), t1 = lrelu(h W1_1^T + b1_1)
    L1.Ahi[0] = phh; L1.Alo[0] = phl; L1.Chi[0] = pt0h; L1.Clo[0] = pt0l;
    L1.bias[0] = b1_0; L1.mat[0] = 0; L1.fpout[0] = 0;
    L1.Ahi[1] = phh; L1.Alo[1] = phl; L1.Chi[1] = pt1h; L1.Clo[1] = pt1l;
    L1.bias[1] = b1_1; L1.mat[1] = 2; L1.fpout[1] = 0;
    L1.nmats = 2; L1.act = 1;

    Jobs L2 = {};      // z0 = t0 W2_0^T, z1 = t1 W2_1^T, h-gates = h Whh^T
    L2.Ahi[0] = pt0h; L2.Alo[0] = pt0l; L2.Chi[0] = pz0h; L2.Clo[0] = pz0l;
    L2.bias[0] = b2_0; L2.mat[0] = 1; L2.fpout[0] = 0;
    L2.Ahi[1] = pt1h; L2.Alo[1] = pt1l; L2.Chi[1] = pz1h; L2.Clo[1] = pz1l;
    L2.bias[1] = b2_1; L2.mat[1] = 3; L2.fpout[1] = 0;
    for (int g = 0; g < 3; g++) {
        L2.Ahi[2 + g] = phh; L2.Alo[2 + g] = phl;
        L2.Cf[2 + g] = pg + (size_t)(3 + g) * GS;
        L2.bias[2 + g] = bhh + g * HD; L2.mat[2 + g] = 7 + g; L2.fpout[2 + g] = 1;
    }
    L2.nmats = 5; L2.act = 0;

    Jobs L4 = {};      // i-gates = inc Wih^T
    for (int g = 0; g < 3; g++) {
        L4.Ahi[g] = pih; L4.Alo[g] = pil;
        L4.Cf[g] = pg + (size_t)g * GS;
        L4.bias[g] = bih + g * HD; L4.mat[g] = 4 + g; L4.fpout[g] = 1;
    }
    L4.nmats = 3; L4.act = 0;

    for (int p = 0; p < PASSES; p++) {
        gemm_multi<<<148, 256, SMEM_TOTAL>>>(L1, tiles, N);
        gemm_multi<<<148, 256, SMEM_TOTAL>>>(L2, tiles, N);
        gather_both<<<gatherBlocks, 256>>>(N);
        gemm_multi<<<148, 256, SMEM_TOTAL>>>(L4, tiles, N);
        gru_gate4<<<2048, 256>>>(pg, N);
    }

    zero_f4<<<16, 256>>>((float4*)pgraph, GMAX * HD / 4);
    seg_sum<<<(N + 255) / 256, 160>>>(gids, pgraph, N);
    mlp_head<<<1, 256>>>(pgraph, ptype, fc1W, fc1b, fc2W, fc2b, fcLW, fcLb,
                         (float*)d_out);
}

// round 15
// speedup vs baseline: 1.4972x; 1.4972x over previous
#include <cuda_runtime.h>
#include <cuda_bf16.h>
#include <math.h>
#include <stdint.h>

// ---------------------------------------------------------------------------
// GGNN forward. GEMMs on tensor cores via portable mma.sync (bf16, fp32 acc)
// with bf16x3 split emulation: C = Ah*Bh + Al*Bh + Ah*Bl  (residual ~2^-18).
// R14 changes (from the 2860us baseline; plane experiment reverted):
//   * gemm warp tiling 4m x 2n -> 2m x 4n (warp = m32 x n40): halves B
//     ldmatrix smem traffic (the measured binding resource), via ldmatrix.x2
//   * merged CSR build kept (verified in R14): 6 launches
// ---------------------------------------------------------------------------

#define HD 150          // feature dim
#define LD 160          // padded activation leading dim (fp32)
#define NMAX 100000
#define EMAX 500000
#define GMAX 16
#define NMATS 10        // W1_0,W2_0,W1_1,W2_1, Wih x3, Whh x3

#define BM 64           // rows per m-tile
#define KTI 10          // k chunks of 16 (K=160, pads are zero)

// smem layout (bytes). W rows padded to 168 bf16 (336B) -> conflict-free
// ldmatrix; A rows padded to 168 floats (672B) -> conflict-free LDS.64.
#define WSTRIDE 336
#define ASTRIDE 672
#define O_WHI 0
#define O_WLO 53760                    // 160*336
#define O_A0  107520
#define O_A1  150528                   // +64*672
#define O_BIAS 193536
#define SMEM_TOTAL 194176

static constexpr size_t GS = (size_t)NMAX * LD;   // gate buffer stride

// ---- scratch (device globals, zero-initialized at module load) ----
__device__ float g_h  [NMAX * LD];
__device__ float g_t0 [NMAX * LD];
__device__ float g_t1 [NMAX * LD];
__device__ float g_z0 [NMAX * LD];
__device__ float g_z1 [NMAX * LD];
__device__ float g_inc[NMAX * LD];
__device__ float g_gate[6 * (size_t)NMAX * LD];   // ir,iz,in,hr,hz,hn
__device__ float g_graph[GMAX * HD];
__device__ __align__(16) __nv_bfloat16 g_Whi[NMATS * LD * LD];  // [mat][n][k]
__device__ __align__(16) __nv_bfloat16 g_Wlo[NMATS * LD * LD];

// CSR (rebuilt every launch; edges are static inputs)
__device__ int g_cnt [2][NMAX];
__device__ int g_off [2][NMAX + 1];
__device__ int g_cur [2][NMAX];
__device__ int g_srcs[2][EMAX];
__device__ int g_bsum[2][128];

// ---------------------------------------------------------------------------
// helpers
// ---------------------------------------------------------------------------
__device__ __forceinline__ uint32_t smem_u32(const void* p) {
    uint32_t a;
    asm("{ .reg .u64 t; cvta.to.shared.u64 t, %1; cvt.u32.u64 %0, t; }"
        : "=r"(a) : "l"(p));
    return a;
}
__device__ __forceinline__ void cp16(uint32_t dst, const void* src) {
    asm volatile("cp.async.cg.shared.global [%0], [%1], 16;"
                 :: "r"(dst), "l"(src));
}
#define CP_COMMIT() asm volatile("cp.async.commit_group;" ::: "memory")
#define CP_WAIT(n)  asm volatile("cp.async.wait_group %0;" :: "n"(n) : "memory")

__device__ __forceinline__ void ldmx2(uint32_t* r, uint32_t addr) {
    asm volatile("ldmatrix.sync.aligned.m8n8.x2.shared.b16 {%0,%1}, [%2];"
                 : "=r"(r[0]), "=r"(r[1]) : "r"(addr));
}
__device__ __forceinline__ void mma16816(float* c, const uint32_t* a,
                                         const uint32_t* b) {
    asm volatile("mma.sync.aligned.m16n8k16.row.col.f32.bf16.bf16.f32 "
                 "{%0,%1,%2,%3}, {%4,%5,%6,%7}, {%8,%9}, {%0,%1,%2,%3};"
                 : "+f"(c[0]), "+f"(c[1]), "+f"(c[2]), "+f"(c[3])
                 : "r"(a[0]), "r"(a[1]), "r"(a[2]), "r"(a[3]),
                   "r"(b[0]), "r"(b[1]));
}
__device__ __forceinline__ uint32_t f2bf2(float a, float b) {
    __nv_bfloat162 h = __floats2bfloat162_rn(a, b);
    return *reinterpret_cast<uint32_t*>(&h);
}
__device__ __forceinline__ uint32_t lo2(float2 v, uint32_t hi) {
    const float hx = __uint_as_float(hi << 16);
    const float hy = __uint_as_float(hi & 0xffff0000u);
    return f2bf2(v.x - hx, v.y - hy);
}

// ---------------------------------------------------------------------------
// Weight pre-split: 10 matrices -> [LD x LD] bf16 hi/lo in global.
// ---------------------------------------------------------------------------
__global__ void make_wsplit(const float* __restrict__ W1_0, const float* __restrict__ W2_0,
                            const float* __restrict__ W1_1, const float* __restrict__ W2_1,
                            const float* __restrict__ Wih,  const float* __restrict__ Whh)
{
    const int total = NMATS * LD * LD;
    for (int idx = blockIdx.x * blockDim.x + threadIdx.x; idx < total;
         idx += gridDim.x * blockDim.x) {
        const int mat = idx / (LD * LD);
        const int rem = idx - mat * (LD * LD);
        const int r = rem / LD;
        const int k = rem - r * LD;
        float v = 0.f;
        if (r < HD && k < HD) {
            if      (mat == 0) v = W1_0[r * HD + k];
            else if (mat == 1) v = W2_0[r * HD + k];
            else if (mat == 2) v = W1_1[r * HD + k];
            else if (mat == 3) v = W2_1[r * HD + k];
            else if (mat <= 6) v = Wih[((mat - 4) * HD + r) * HD + k];
            else               v = Whh[((mat - 7) * HD + r) * HD + k];
        }
        __nv_bfloat16 hi = __float2bfloat16_rn(v);
        __nv_bfloat16 lo = __float2bfloat16_rn(v - __bfloat162float(hi));
        g_Whi[idx] = hi;
        g_Wlo[idx] = lo;
    }
}

// ---------------------------------------------------------------------------
// Multi-matrix persistent tensor-core GEMM.
//   For each job m: C[m][M x 150(pad160)] = act(A[m] @ W[mat[m]].T + bias[m])
// 8 warps = 2m(32 rows) x 4n(40 cols): each B fragment feeds 2 MMAs,
// halving ldmatrix smem traffic vs the 4m x 2n layout.
// ---------------------------------------------------------------------------
struct Jobs {
    const float* A[6];
    float*       C[6];
    const float* bias[6];
    int          mat[6];
    int          nmats;
    int          act;
};

__global__ __launch_bounds__(256, 1)
void gemm_multi(Jobs j, int tiles, int M)
{
    extern __shared__ char smem[];
    const uint32_t sb = smem_u32(smem);
    const int tid  = threadIdx.x;
    const int wid  = tid >> 5;
    const int lane = tid & 31;
    const int warpM = wid & 1;          // m32 slice within BM=64
    const int warpN = wid >> 1;         // n40 quarter

    const int units = j.nmats * tiles;
    const int u0 = (int)(((long long)units * blockIdx.x) / gridDim.x);
    const int u1 = (int)(((long long)units * (blockIdx.x + 1)) / gridDim.x);
    if (u0 >= u1) return;

    // B ldmatrix.x2 addresses: 5 n8 tiles; lanes 0-7 rows@k0, 8-15 rows@k8
    const int rB2 = lane & 7;
    const int kB2 = ((lane >> 3) & 1) << 3;
    uint32_t bAddr[5];
    #pragma unroll
    for (int p = 0; p < 5; p++)
        bAddr[p] = sb + O_WHI + (warpN * 40 + p * 8 + rB2) * WSTRIDE + kB2 * 2;

    const int rowA = warpM * 32 + (lane >> 2);
    const int kA   = (lane & 3) * 2;

    // ---- prologue: A(u0) into buf0 ----
    {
        const int m0 = u0 / tiles, t0 = u0 - m0 * tiles;
        const float* A = j.A[m0];
        for (int jj = tid; jj < BM * 40; jj += 256) {
            const int r = jj / 40, u = jj - r * 40;
            const int grow = min(t0 * BM + r, M - 1);
            cp16(sb + O_A0 + r * ASTRIDE + u * 16, A + (size_t)grow * LD + u * 4);
        }
        CP_COMMIT();
    }

    int curMat = -1;
    int i = 0;
    for (int u = u0; u < u1; u++, i++) {
        const int m = u / tiles;
        const int t = u - m * tiles;
        const int cur = i & 1;

        if (m != curMat) {                 // (re)load W + bias for this job
            curMat = m;
            const int mat = j.mat[m];
            const __nv_bfloat16* Wh = g_Whi + (size_t)mat * LD * LD;
            const __nv_bfloat16* Wl = g_Wlo + (size_t)mat * LD * LD;
            for (int jj = tid; jj < 2 * LD * 20; jj += 256) {
                const int s  = (jj >= LD * 20);
                const int j2 = s ? (jj - LD * 20) : jj;
                const int r  = j2 / 20;
                const int uu = j2 - r * 20;
                cp16(sb + (s ? O_WLO : O_WHI) + r * WSTRIDE + uu * 16,
                     (s ? Wl : Wh) + (size_t)r * LD + uu * 8);
            }
            CP_COMMIT();
            const float* bp = j.bias[m];
            for (int c = tid; c < LD; c += 256)
                *reinterpret_cast<float*>(smem + O_BIAS + c * 4) =
                    (c < HD) ? bp[c] : 0.f;
        }

        // ---- prefetch A(u+1) into the other buffer ----
        if (u + 1 < u1) {
            const int mn = (u + 1) / tiles;
            const int tn = (u + 1) - mn * tiles;
            const float* A = j.A[mn];
            const uint32_t aoff = cur ? O_A0 : O_A1;
            for (int jj = tid; jj < BM * 40; jj += 256) {
                const int r = jj / 40, uu = jj - r * 40;
                const int grow = min(tn * BM + r, M - 1);
                cp16(sb + aoff + r * ASTRIDE + uu * 16,
                     A + (size_t)grow * LD + uu * 4);
            }
            CP_COMMIT();
            CP_WAIT(1);    // A(u) + W done; A(u+1) may stay in flight
        } else {
            CP_WAIT(0);
        }
        __syncthreads();

        const float* sA = reinterpret_cast<const float*>(
            smem + (cur ? O_A1 : O_A0));

        float acc[2][5][4];
        #pragma unroll
        for (int mi = 0; mi < 2; mi++)
            #pragma unroll
            for (int p = 0; p < 5; p++)
                #pragma unroll
                for (int q = 0; q < 4; q++) acc[mi][p][q] = 0.f;

        #pragma unroll
        for (int kt = 0; kt < KTI; kt++) {
            // A fragments for the two m16 tiles, split to bf16 hi/lo
            uint32_t ah[2][4], al[2][4];
            #pragma unroll
            for (int mi = 0; mi < 2; mi++) {
                const float* ap = sA + (rowA + mi * 16) * 168 + kt * 16 + kA;
                const float2 v00 = *reinterpret_cast<const float2*>(ap);
                const float2 v10 = *reinterpret_cast<const float2*>(ap + 8 * 168);
                const float2 v01 = *reinterpret_cast<const float2*>(ap + 8);
                const float2 v11 = *reinterpret_cast<const float2*>(ap + 8 * 168 + 8);
                ah[mi][0] = f2bf2(v00.x, v00.y);  al[mi][0] = lo2(v00, ah[mi][0]);
                ah[mi][1] = f2bf2(v10.x, v10.y);  al[mi][1] = lo2(v10, ah[mi][1]);
                ah[mi][2] = f2bf2(v01.x, v01.y);  al[mi][2] = lo2(v01, ah[mi][2]);
                ah[mi][3] = f2bf2(v11.x, v11.y);  al[mi][3] = lo2(v11, ah[mi][3]);
            }

            // product-major order: 10 independent MMAs between acc reuses;
            // each B fragment feeds both m16 tiles (2x reuse).
            uint32_t bfr[5][2];
            #pragma unroll
            for (int p = 0; p < 5; p++) ldmx2(bfr[p], bAddr[p] + kt * 32);
            #pragma unroll
            for (int p = 0; p < 5; p++) {
                mma16816(acc[0][p], ah[0], bfr[p]);
                mma16816(acc[1][p], ah[1], bfr[p]);
            }
            #pragma unroll
            for (int p = 0; p < 5; p++) {
                mma16816(acc[0][p], al[0], bfr[p]);
                mma16816(acc[1][p], al[1], bfr[p]);
            }
            #pragma unroll
            for (int p = 0; p < 5; p++)
                ldmx2(bfr[p], bAddr[p] + kt * 32 + (O_WLO - O_WHI));
            #pragma unroll
            for (int p = 0; p < 5; p++) {
                mma16816(acc[0][p], ah[0], bfr[p]);
                mma16816(acc[1][p], ah[1], bfr[p]);
            }
        }

        // ---- epilogue: bias + act, write fp32 ----
        {
            float* Cp = j.C[m];
            #pragma unroll
            for (int mi = 0; mi < 2; mi++) {
                const int r0 = t * BM + warpM * 32 + mi * 16 + (lane >> 2);
                #pragma unroll
                for (int p = 0; p < 5; p++) {
                    const int c0 = warpN * 40 + p * 8 + (lane & 3) * 2;
                    const float b0 = *reinterpret_cast<float*>(smem + O_BIAS + c0 * 4);
                    const float b1 = *reinterpret_cast<float*>(smem + O_BIAS + (c0 + 1) * 4);
                    float x0 = acc[mi][p][0] + b0, x1 = acc[mi][p][1] + b1;
                    float x2 = acc[mi][p][2] + b0, x3 = acc[mi][p][3] + b1;
                    if (j.act) {
                        x0 = x0 > 0.f ? x0 : 0.01f * x0;
                        x1 = x1 > 0.f ? x1 : 0.01f * x1;
                        x2 = x2 > 0.f ? x2 : 0.01f * x2;
                        x3 = x3 > 0.f ? x3 : 0.01f * x3;
                    }
                    if (r0 < M)
                        *reinterpret_cast<float2*>(Cp + (size_t)r0 * LD + c0) =
                            make_float2(x0, x1);
                    if (r0 + 8 < M)
                        *reinterpret_cast<float2*>(Cp + (size_t)(r0 + 8) * LD + c0) =
                            make_float2(x2, x3);
                }
            }
        }
        __syncthreads();   // protect A/W/bias buffers before next iteration
    }
}

// ---------------------------------------------------------------------------
// CSR build (merged, 6 launches). counts -> offsets -> cursors -> fill.
// ---------------------------------------------------------------------------
#define SCAN_BLK 1024
#define SCAN_NB  ((NMAX + SCAN_BLK - 1) / SCAN_BLK)   // 98

__global__ void csr_zero()
{
    int* c = &g_cnt[0][0];
    for (int i = blockIdx.x * blockDim.x + threadIdx.x; i < 2 * NMAX;
         i += gridDim.x * blockDim.x) c[i] = 0;
}
__global__ void csr_hist2(const int* __restrict__ e0, int E0,
                          const int* __restrict__ e1, int E1)
{
    const int total = E0 + E1;
    for (int i = blockIdx.x * blockDim.x + threadIdx.x; i < total;
         i += gridDim.x * blockDim.x) {
        if (i < E0) atomicAdd(&g_cnt[0][e0[2 * i]], 1);
        else        atomicAdd(&g_cnt[1][e1[2 * (i - E0)]], 1);
    }
}
__global__ void csr_scan1()
{
    const int s = blockIdx.y;
    __shared__ int sh[SCAN_BLK];
    const int t = threadIdx.x;
    const int idx = blockIdx.x * SCAN_BLK + t;
    int v = (idx < NMAX) ? g_cnt[s][idx] : 0;
    sh[t] = v; __syncthreads();
    #pragma unroll
    for (int d = 1; d < SCAN_BLK; d <<= 1) {
        int x = (t >= d) ? sh[t - d] : 0;
        __syncthreads();
        sh[t] += x;
        __syncthreads();
    }
    if (idx < NMAX) g_off[s][idx + 1] = sh[t];
    if (t == SCAN_BLK - 1) g_bsum[s][blockIdx.x] = sh[t];
    if (idx == 0) g_off[s][0] = 0;
}
__global__ void csr_scan2both()
{
    if (threadIdx.x == 0) {
        for (int s = 0; s < 2; s++) {
            int acc = 0;
            for (int b = 0; b < SCAN_NB; b++) {
                int t = g_bsum[s][b];
                g_bsum[s][b] = acc;
                acc += t;
            }
        }
    }
}
__global__ void csr_scan3c()   // finalize offsets + write cursors
{
    const int s = blockIdx.y;
    for (int idx = blockIdx.x * blockDim.x + threadIdx.x; idx < NMAX;
         idx += gridDim.x * blockDim.x) {
        const int v = g_off[s][idx + 1] + g_bsum[s][idx >> 10];
        g_off[s][idx + 1] = v;
        if (idx + 1 < NMAX) g_cur[s][idx + 1] = v;
        if (idx == 0) g_cur[s][0] = 0;
    }
}
__global__ void csr_fill2(const int* __restrict__ e0, int E0,
                          const int* __restrict__ e1, int E1)
{
    const int total = E0 + E1;
    for (int i = blockIdx.x * blockDim.x + threadIdx.x; i < total;
         i += gridDim.x * blockDim.x) {
        const int s = (i < E0) ? 0 : 1;
        const int* e = (s == 0) ? e0 : e1;
        const int k = (s == 0) ? i : i - E0;
        const int dst = e[2 * k];
        const int src = e[2 * k + 1];
        const int slot = atomicAdd(&g_cur[s][dst], 1);
        g_srcs[s][slot] = src;
    }
}

// ---------------------------------------------------------------------------
// Fused gather over BOTH edge sets:
//   inc[v] = sum_{e in set0(v)} z0[src(e)] + sum_{e in set1(v)} z1[src(e)]
// One warp per node, register accumulation, one plain store (no read).
// ---------------------------------------------------------------------------
__global__ void gather_both(const float* __restrict__ z0,
                            const float* __restrict__ z1,
                            float* __restrict__ inc, int N)
{
    const int v = (int)((blockIdx.x * blockDim.x + threadIdx.x) >> 5);
    const int lane = threadIdx.x & 31;
    if (v >= N) return;
    float4 a0 = make_float4(0.f, 0.f, 0.f, 0.f);
    float4 a1 = a0;
    #pragma unroll
    for (int s = 0; s < 2; s++) {
        const float* z = s ? z1 : z0;
        const int st = g_off[s][v];
        const int en = g_off[s][v + 1];
        for (int i = st; i < en; i++) {
            const int src = g_srcs[s][i];
            const float4* zr = reinterpret_cast<const float4*>(z + (size_t)src * LD);
            const float4 b = zr[lane];
            a0.x += b.x; a0.y += b.y; a0.z += b.z; a0.w += b.w;
            if (lane < 8) {
                const float4 c = zr[lane + 32];
                a1.x += c.x; a1.y += c.y; a1.z += c.z; a1.w += c.w;
            }
        }
    }
    float4* ir = reinterpret_cast<float4*>(inc + (size_t)v * LD);
    ir[lane] = a0;
    if (lane < 8) ir[lane + 32] = a1;
}

__global__ void zero_f4(float4* __restrict__ p, int n4)
{
    int i = blockIdx.x * blockDim.x + threadIdx.x;
    const int stride = gridDim.x * blockDim.x;
    for (; i < n4; i += stride) p[i] = make_float4(0.f, 0.f, 0.f, 0.f);
}

__global__ void init_h(const float* __restrict__ nodes,
                       float* __restrict__ h, int N)
{
    int idx = blockIdx.x * blockDim.x + threadIdx.x;
    const int total = N * LD;
    const int stride = gridDim.x * blockDim.x;
    for (; idx < total; idx += stride) {
        const int r = idx / LD, c = idx - r * LD;
        h[idx] = (c < HD) ? nodes[r * HD + c] : 0.f;
    }
}

// GRU gate combine, float4-vectorized: h = (1-z)*tanh(in + r*hn) + z*h.
// Pads: all gate pads are 0 -> h pad stays 0 (0.5*0 + 0.5*0).
__global__ void gru_gate4(const float* __restrict__ gates,
                          float* __restrict__ h, int N)
{
    const int n4 = N * (LD / 4);
    const float4* gir = reinterpret_cast<const float4*>(gates + 0 * GS);
    const float4* giz = reinterpret_cast<const float4*>(gates + 1 * GS);
    const float4* gin = reinterpret_cast<const float4*>(gates + 2 * GS);
    const float4* ghr = reinterpret_cast<const float4*>(gates + 3 * GS);
    const float4* ghz = reinterpret_cast<const float4*>(gates + 4 * GS);
    const float4* ghn = reinterpret_cast<const float4*>(gates + 5 * GS);
    float4* hp = reinterpret_cast<float4*>(h);
    int idx = blockIdx.x * blockDim.x + threadIdx.x;
    const int stride = gridDim.x * blockDim.x;
    for (; idx < n4; idx += stride) {
        const float4 ir = gir[idx], iz = giz[idx], in_ = gin[idx];
        const float4 hr = ghr[idx], hz = ghz[idx], hn = ghn[idx];
        float4 ho = hp[idx];
        #pragma unroll
        for (int c = 0; c < 4; c++) {
            const float irv = (&ir.x)[c], izv = (&iz.x)[c], inv = (&in_.x)[c];
            const float hrv = (&hr.x)[c], hzv = (&hz.x)[c], hnv = (&hn.x)[c];
            const float r  = 1.f / (1.f + expf(-(irv + hrv)));
            const float zz = 1.f / (1.f + expf(-(izv + hzv)));
            const float n  = tanhf(inv + r * hnv);
            (&ho.x)[c] = (1.f - zz) * n + zz * (&ho.x)[c];
        }
        hp[idx] = ho;
    }
}

// Segment sum over sorted graph_ids.
__global__ void seg_sum(const float* __restrict__ h,
                        const int* __restrict__ gid,
                        float* __restrict__ gout, int N)
{
    const int f = threadIdx.x;
    const int r0 = blockIdx.x * 256;
    const int r1 = min(r0 + 256, N);
    float acc = 0.f;
    int cur = -1;
    for (int r = r0; r < r1; r++) {
        const int id = gid[r];
        if (id != cur) {
            if (cur >= 0 && f < HD) atomicAdd(&gout[cur * HD + f], acc);
            acc = 0.f; cur = id;
        }
        if (f < HD) acc += h[(size_t)r * LD + f];
    }
    if (cur >= 0 && f < HD) atomicAdd(&gout[cur * HD + f], acc);
}

// Head MLP (16 rows): one block.
__global__ void mlp_head(const float* __restrict__ gg,
                         const float* __restrict__ ptype,
                         const float* __restrict__ fc1W, const float* __restrict__ fc1b,
                         const float* __restrict__ fc2W, const float* __restrict__ fc2b,
                         const float* __restrict__ fcLW, const float* __restrict__ fcLb,
                         float* __restrict__ out)
{
    __shared__ float sx [GMAX * 151];
    __shared__ float sy1[GMAX * 80];
    __shared__ float sy2[GMAX * 80];
    const int tid = threadIdx.x;

    for (int p = tid; p < GMAX * HD; p += blockDim.x) {
        const int g = p / HD, k = p - g * HD;
        float lg = logf(gg[p]);
        if (isnan(lg)) lg = 0.f;
        sx[g * 151 + k] = fmaxf(lg, 0.f);
    }
    for (int p = tid; p < GMAX; p += blockDim.x) sx[p * 151 + 150] = ptype[p];
    __syncthreads();

    for (int p = tid; p < GMAX * 80; p += blockDim.x) {
        const int g = p / 80, o = p - g * 80;
        float s = fc1b[o];
        for (int k = 0; k < 151; k++) s += fc1W[o * 151 + k] * sx[g * 151 + k];
        sy1[g * 80 + o] = s > 0.f ? s : 0.01f * s;
    }
    __syncthreads();

    for (int p = tid; p < GMAX * 80; p += blockDim.x) {
        const int g = p / 80, o = p - g * 80;
        float s = fc2b[o];
        for (int k = 0; k < 80; k++) s += fc2W[o * 80 + k] * sy1[g * 80 + k];
        sy2[g * 80 + o] = s > 0.f ? s : 0.01f * s;
    }
    __syncthreads();

    for (int p = tid; p < GMAX * 10; p += blockDim.x) {
        const int g = p / 10, o = p - g * 10;
        float s = fcLb[o];
        for (int k = 0; k < 80; k++) s += fcLW[o * 80 + k] * sy2[g * 80 + k];
        out[g * 10 + o] = s;
    }
}

// ---------------------------------------------------------------------------
extern "C" void kernel_launch(void* const* d_in, const int* in_sizes, int n_in,
                              void* d_out, int out_size)
{
    const float* nodes = (const float*)d_in[0];
    const float* ptype = (const float*)d_in[1];
    const float* W1_0  = (const float*)d_in[2];  const float* b1_0 = (const float*)d_in[3];
    const float* W2_0  = (const float*)d_in[4];  const float* b2_0 = (const float*)d_in[5];
    const float* W1_1  = (const float*)d_in[6];  const float* b1_1 = (const float*)d_in[7];
    const float* W2_1  = (const float*)d_in[8];  const float* b2_1 = (const float*)d_in[9];
    const float* Wih   = (const float*)d_in[10]; const float* bih  = (const float*)d_in[11];
    const float* Whh   = (const float*)d_in[12]; const float* bhh  = (const float*)d_in[13];
    const float* fc1W  = (const float*)d_in[14]; const float* fc1b = (const float*)d_in[15];
    const float* fc2W  = (const float*)d_in[16]; const float* fc2b = (const float*)d_in[17];
    const float* fcLW  = (const float*)d_in[18]; const float* fcLb = (const float*)d_in[19];
    const int* edges0  = (const int*)d_in[20];
    const int* edges1  = (const int*)d_in[21];
    const int* gids    = (const int*)d_in[22];

    const int N  = in_sizes[0] / HD;
    const int E0 = in_sizes[20] / 2;
    const int E1 = in_sizes[21] / 2;
    const int PASSES = 4;

    float *ph, *pt0, *pt1, *pz0, *pz1, *pinc, *pg, *pgraph;
    cudaGetSymbolAddress((void**)&ph,     g_h);
    cudaGetSymbolAddress((void**)&pt0,    g_t0);
    cudaGetSymbolAddress((void**)&pt1,    g_t1);
    cudaGetSymbolAddress((void**)&pz0,    g_z0);
    cudaGetSymbolAddress((void**)&pz1,    g_z1);
    cudaGetSymbolAddress((void**)&pinc,   g_inc);
    cudaGetSymbolAddress((void**)&pg,     g_gate);
    cudaGetSymbolAddress((void**)&pgraph, g_graph);

    cudaFuncSetAttribute(gemm_multi, cudaFuncAttributeMaxDynamicSharedMemorySize,
                         SMEM_TOTAL);

    const int tiles = (N + BM - 1) / BM;
    const int gatherBlocks = (N * 32 + 255) / 256;

    make_wsplit<<<256, 256>>>(W1_0, W2_0, W1_1, W2_1, Wih, Whh);
    init_h<<<2048, 256>>>(nodes, ph, N);

    // ---- CSR build (both edge sets, merged launches) ----
    csr_zero<<<256, 256>>>();
    csr_hist2<<<512, 256>>>(edges0, E0, edges1, E1);
    csr_scan1<<<dim3(SCAN_NB, 2), SCAN_BLK>>>();
    csr_scan2both<<<1, 32>>>();
    csr_scan3c<<<dim3(128, 2), 256>>>();
    csr_fill2<<<512, 256>>>(edges0, E0, edges1, E1);

    // ---- job tables ----
    Jobs L1 = {};      // t0 = lrelu(h W1_0^T + b1_0), t1 = lrelu(h W1_1^T + b1_1)
    L1.A[0] = ph;  L1.C[0] = pt0; L1.bias[0] = b1_0; L1.mat[0] = 0;
    L1.A[1] = ph;  L1.C[1] = pt1; L1.bias[1] = b1_1; L1.mat[1] = 2;
    L1.nmats = 2;  L1.act = 1;

    Jobs L2 = {};      // z0 = t0 W2_0^T, z1 = t1 W2_1^T, gh = h Whh^T (3 gates)
    L2.A[0] = pt0; L2.C[0] = pz0;          L2.bias[0] = b2_0;     L2.mat[0] = 1;
    L2.A[1] = pt1; L2.C[1] = pz1;          L2.bias[1] = b2_1;     L2.mat[1] = 3;
    L2.A[2] = ph;  L2.C[2] = pg + 3 * GS;  L2.bias[2] = bhh;      L2.mat[2] = 7;
    L2.A[3] = ph;  L2.C[3] = pg + 4 * GS;  L2.bias[3] = bhh + HD; L2.mat[3] = 8;
    L2.A[4] = ph;  L2.C[4] = pg + 5 * GS;  L2.bias[4] = bhh + 2 * HD; L2.mat[4] = 9;
    L2.nmats = 5;  L2.act = 0;

    Jobs L4 = {};      // gi = inc Wih^T (3 gates)
    L4.A[0] = pinc; L4.C[0] = pg + 0 * GS; L4.bias[0] = bih;          L4.mat[0] = 4;
    L4.A[1] = pinc; L4.C[1] = pg + 1 * GS; L4.bias[1] = bih + HD;     L4.mat[1] = 5;
    L4.A[2] = pinc; L4.C[2] = pg + 2 * GS; L4.bias[2] = bih + 2 * HD; L4.mat[2] = 6;
    L4.nmats = 3;  L4.act = 0;

    for (int p = 0; p < PASSES; p++) {
        gemm_multi<<<148, 256, SMEM_TOTAL>>>(L1, tiles, N);
        gemm_multi<<<148, 256, SMEM_TOTAL>>>(L2, tiles, N);
        gather_both<<<gatherBlocks, 256>>>(pz0, pz1, pinc, N);
        gemm_multi<<<148, 256, SMEM_TOTAL>>>(L4, tiles, N);
        gru_gate4<<<2048, 256>>>(pg, ph, N);
    }

    zero_f4<<<16, 256>>>((float4*)pgraph, GMAX * HD / 4);
    seg_sum<<<(N + 255) / 256, 160>>>(ph, gids, pgraph, N);
    mlp_head<<<1, 256>>>(pgraph, ptype, fc1W, fc1b, fc2W, fc2b, fcLW, fcLb,
                         (float*)d_out);
}